// round 15
// baseline (speedup 1.0000x reference)
#include <cuda_runtime.h>
#include <math.h>

#define BB 32
#define TT 200
#define TM 199
#define NN (BB*TM)        // 6368
#define DD 100
#define KK 10
#define NE2 4800          // unique (sk,s) pairs = NUM_S*NS
#define NE1 1200          // unique skills = NUM_S

#define MB0 100           // NE2/48
#define MB1 25            // NE1/48
#define NB2 133           // ceil(NN/48)
#define NBD 266           // ceil(NN/24)
#define NGATE 597
#define NSCOR 800
#define NBDS (NBD+NSCOR)  // fused stageD + scores grid

typedef unsigned long long ull;

// ---------------- scratch ----------------
__device__ float g_buf[5814400];
__device__ int   g_topk[NN*KK];

static constexpr size_t OFF_E2P = 0;          // NE2*100 = 480000
static constexpr size_t OFF_E1T = 480000;     // NE1*100 = 120000
static constexpr size_t OFF_E0A = 600000;     // NN*100 = 636800
static constexpr size_t OFF_E1B = 1236800;    // NE1*100
static constexpr size_t OFF_E0B = 1356800;    // NN*100
static constexpr size_t OFF_AGG = 1993600;    // NN*100
static constexpr size_t OFF_L   = 2630400;    // NN*100
static constexpr size_t OFF_G   = 3267200;    // NN*400

// ---------------- helpers ----------------
__device__ __forceinline__ void fma2(ull& a, ull x, ull w){
    asm("fma.rn.f32x2 %0, %1, %2, %0;" : "+l"(a) : "l"(x), "l"(w));
}
__device__ __forceinline__ float unpack_sum(ull a){
    float lo = __int_as_float((int)(unsigned int)a);
    float hi = __int_as_float((int)(unsigned int)(a >> 32));
    return lo + hi;
}
__device__ __forceinline__ float ftanh(float x){
    float e = __expf(2.f*x);
    return 1.f - __fdividef(2.f, e + 1.f);
}
__device__ __forceinline__ float fsig(float x){
    return __fdividef(1.f, 1.f + __expf(-x));
}

// load 100x100 W into smem pitch 102 (51 ull words; conflict-free LDS.64)
__device__ __forceinline__ void loadW100(const float* __restrict__ W, float* Ws, int tid){
    for (int j = tid; j < 2500; j += 256){
        float4 v = ((const float4*)W)[j];
        int b4 = 4*j; int o = b4/100; int d = b4 - o*100;
        float2* ws = (float2*)&Ws[o*102 + d];
        ws[0] = make_float2(v.x, v.y);
        ws[1] = make_float2(v.z, v.w);
    }
}

// Software-pipelined KR-rows-per-thread 100-d FFMA core.
template<int KR>
__device__ __forceinline__ void core100p(const float* Ws, const float* Xs, int wy,
                                         const int* col, ull (*acc)[4]){
    const ull* WsU = (const ull*)Ws;
    const ull* XsU = (const ull*)Xs;
    const int xbase = wy*KR*52;
    ull w[4], x[KR], nw[4], nx[KR];
    #pragma unroll
    for (int c = 0; c < 4; c++) w[c] = WsU[col[c]*51];
    #pragma unroll
    for (int k = 0; k < KR; k++) x[k] = XsU[xbase + k*52];
    #pragma unroll 1
    for (int dw = 0; dw < 50; dw++){
        int dn = dw + 1;
        #pragma unroll
        for (int c = 0; c < 4; c++) nw[c] = WsU[col[c]*51 + dn];
        #pragma unroll
        for (int k = 0; k < KR; k++) nx[k] = XsU[xbase + k*52 + dn];
        #pragma unroll
        for (int k = 0; k < KR; k++)
            #pragma unroll
            for (int c = 0; c < 4; c++)
                fma2(acc[k][c], x[k], w[c]);
        #pragma unroll
        for (int c = 0; c < 4; c++) w[c] = nw[c];
        #pragma unroll
        for (int k = 0; k < KR; k++) x[k] = nx[k];
    }
}

// ---------------- stage B: deduped gather + affine ----------------

__global__ __launch_bounds__(256) void stageB_k(
    const int* __restrict__ question, const int* __restrict__ q_nb,
    const int* __restrict__ s_nb, const float* __restrict__ emb_q,
    const float* __restrict__ emb_s, const float* __restrict__ aggW,
    const float* __restrict__ aggb, float* __restrict__ E2P,
    float* __restrict__ E1T, float* __restrict__ E0){
    extern __shared__ float sm[];
    float* Ws = sm;            // 10200
    float* Xs = sm + 10200;    // 48*104
    float* bs = Xs + 48*104;   // 100
    int tid = threadIdx.x, wy = tid >> 5, lane = tid & 31;
    int bid = blockIdx.x;

    int seg, r0, R; const float* W; const float* bias; float* Y;
    if (bid < MB0)            { seg=0; r0=bid*48;           R=NE2; W=aggW+20000; bias=aggb+200; Y=E2P; }
    else if (bid < MB0+MB1)   { seg=1; r0=(bid-MB0)*48;     R=NE1; W=aggW+10000; bias=aggb+100; Y=E1T; }
    else                      { seg=2; r0=(bid-MB0-MB1)*48; R=NN;  W=aggW;       bias=aggb;     Y=E0; }

    loadW100(W, Ws, tid);
    if (tid < 100) bs[tid] = bias[tid];

    for (int rr = wy; rr < 48; rr += 8){
        if (lane < 25){
            int r = r0 + rr;
            float4 val = make_float4(0.f,0.f,0.f,0.f);
            if (r < R){
                const float* basep; const int* nb; const float* tbl;
                if (seg == 0){
                    int q2 = s_nb[r];
                    basep = emb_q + (size_t)q2*DD; nb = q_nb + q2*4; tbl = emb_s;
                } else if (seg == 1){
                    basep = emb_s + (size_t)r*DD; nb = s_nb + r*4; tbl = emb_q;
                } else {
                    int b = r / TM, t = r - b*TM;
                    int q = question[b*TT + t];
                    basep = emb_q + (size_t)q*DD; nb = q_nb + q*4; tbl = emb_s;
                }
                int i0 = nb[0], i1 = nb[1], i2 = nb[2], i3 = nb[3];
                float4 bb = ((const float4*)basep)[lane];
                float4 a = ((const float4*)(tbl + (size_t)i0*DD))[lane];
                float4 c = ((const float4*)(tbl + (size_t)i1*DD))[lane];
                float4 d = ((const float4*)(tbl + (size_t)i2*DD))[lane];
                float4 e = ((const float4*)(tbl + (size_t)i3*DD))[lane];
                val.x = bb.x + 0.25f*(a.x+c.x+d.x+e.x);
                val.y = bb.y + 0.25f*(a.y+c.y+d.y+e.y);
                val.z = bb.z + 0.25f*(a.z+c.z+d.z+e.z);
                val.w = bb.w + 0.25f*(a.w+c.w+d.w+e.w);
            }
            *(float4*)&Xs[rr*104 + 4*lane] = val;
        }
    }
    __syncthreads();

    int c3 = (lane < 4) ? 96 + lane : 96;
    int col[4] = {lane, lane+32, lane+64, c3};
    ull acc[6][4];
    #pragma unroll
    for (int k = 0; k < 6; k++)
        #pragma unroll
        for (int c = 0; c < 4; c++) acc[k][c] = 0ull;
    core100p<6>(Ws, Xs, wy, col, acc);

    #pragma unroll
    for (int k = 0; k < 6; k++){
        int r = r0 + wy*6 + k;
        if (r >= R) continue;
        float* yo = Y + (size_t)r*100;
        yo[col[0]] = ftanh(unpack_sum(acc[k][0]) + bs[col[0]]);
        yo[col[1]] = ftanh(unpack_sum(acc[k][1]) + bs[col[1]]);
        yo[col[2]] = ftanh(unpack_sum(acc[k][2]) + bs[col[2]]);
        if (lane < 4) yo[col[3]] = ftanh(unpack_sum(acc[k][3]) + bs[col[3]]);
    }
}

// ---------------- stage C ----------------

__global__ __launch_bounds__(256) void stageC_k(
    const int* __restrict__ question, const int* __restrict__ q_nb,
    const float* __restrict__ E1T, const float* __restrict__ E2P,
    const float* __restrict__ E0a,
    const float* __restrict__ aggW, const float* __restrict__ aggb,
    float* __restrict__ E1bT, float* __restrict__ E0b){
    extern __shared__ float sm[];
    float* Ws = sm;
    float* Xs = sm + 10200;
    float* bs = Xs + 48*104;
    int tid = threadIdx.x, wy = tid >> 5, lane = tid & 31;
    int bid = blockIdx.x;

    int seg, r0, R; const float* W; const float* bias; float* Y;
    if (bid < MB1){ seg=1; r0=bid*48;        R=NE1; W=aggW+10000; bias=aggb+100; Y=E1bT; }
    else          { seg=2; r0=(bid-MB1)*48;  R=NN;  W=aggW;       bias=aggb;     Y=E0b; }

    loadW100(W, Ws, tid);
    if (tid < 100) bs[tid] = bias[tid];

    for (int rr = wy; rr < 48; rr += 8){
        if (lane < 25){
            int r = r0 + rr;
            float4 val = make_float4(0.f,0.f,0.f,0.f);
            if (r < R){
                float4 a, c, d4, e, bb;
                if (seg == 1){
                    const float4* kp = (const float4*)(E2P + (size_t)r*400);
                    a = kp[lane]; c = kp[25+lane]; d4 = kp[50+lane]; e = kp[75+lane];
                    bb = ((const float4*)(E1T + (size_t)r*100))[lane];
                } else {
                    int b = r / TM, t = r - b*TM;
                    int q = question[b*TT + t];
                    const int* nb = q_nb + q*4;
                    a  = ((const float4*)(E1T + (size_t)nb[0]*100))[lane];
                    c  = ((const float4*)(E1T + (size_t)nb[1]*100))[lane];
                    d4 = ((const float4*)(E1T + (size_t)nb[2]*100))[lane];
                    e  = ((const float4*)(E1T + (size_t)nb[3]*100))[lane];
                    bb = ((const float4*)(E0a + (size_t)r*100))[lane];
                }
                val.x = bb.x + 0.25f*(a.x+c.x+d4.x+e.x);
                val.y = bb.y + 0.25f*(a.y+c.y+d4.y+e.y);
                val.z = bb.z + 0.25f*(a.z+c.z+d4.z+e.z);
                val.w = bb.w + 0.25f*(a.w+c.w+d4.w+e.w);
            }
            *(float4*)&Xs[rr*104 + 4*lane] = val;
        }
    }
    __syncthreads();

    int c3 = (lane < 4) ? 96 + lane : 96;
    int col[4] = {lane, lane+32, lane+64, c3};
    ull acc[6][4];
    #pragma unroll
    for (int k = 0; k < 6; k++)
        #pragma unroll
        for (int c = 0; c < 4; c++) acc[k][c] = 0ull;
    core100p<6>(Ws, Xs, wy, col, acc);

    #pragma unroll
    for (int k = 0; k < 6; k++){
        int r = r0 + wy*6 + k;
        if (r >= R) continue;
        float* yo = Y + (size_t)r*100;
        yo[col[0]] = ftanh(unpack_sum(acc[k][0]) + bs[col[0]]);
        yo[col[1]] = ftanh(unpack_sum(acc[k][1]) + bs[col[1]]);
        yo[col[2]] = ftanh(unpack_sum(acc[k][2]) + bs[col[2]]);
        if (lane < 4) yo[col[3]] = ftanh(unpack_sum(acc[k][3]) + bs[col[3]]);
    }
}

// ---------------- FUSED stage D + scores/top-10 ----------------
// blocks [0,NBD): chained double affine (24-row tiles, kids gathered from E1bT)
// blocks [NBD,NBDS): scores + top-10 (independent of agg chain)

__global__ __launch_bounds__(256) void stageDS_k(
    const int* __restrict__ question, const int* __restrict__ q_nb,
    const float* __restrict__ E0b, const float* __restrict__ E1bT,
    const float* __restrict__ aggW, const float* __restrict__ aggb,
    const float* __restrict__ aggLW, const float* __restrict__ aggLb,
    const float* __restrict__ emb_q,
    float* __restrict__ AGG, int* __restrict__ topk){
    extern __shared__ float sm[];
    int tid = threadIdx.x, wy = tid >> 5, lane = tid & 31;
    int bid = blockIdx.x;

    if (bid < NBD){
        // ---- stage D branch ----
        float* Ws = sm;            // 10200
        float* Xs = sm + 10200;    // 24*104
        float* bs = Xs + 24*104;   // 100
        int r0 = bid * 24;

        loadW100(aggW, Ws, tid);
        if (tid < 100) bs[tid] = aggb[tid];

        for (int rr = wy; rr < 24; rr += 8){
            if (lane < 25){
                int r = r0 + rr;
                float4 val = make_float4(0.f,0.f,0.f,0.f);
                if (r < NN){
                    int b = r / TM, t = r - b*TM;
                    int q = question[b*TT + t];
                    const int* nb = q_nb + q*4;
                    float4 a  = ((const float4*)(E1bT + (size_t)nb[0]*100))[lane];
                    float4 c  = ((const float4*)(E1bT + (size_t)nb[1]*100))[lane];
                    float4 d4 = ((const float4*)(E1bT + (size_t)nb[2]*100))[lane];
                    float4 e  = ((const float4*)(E1bT + (size_t)nb[3]*100))[lane];
                    float4 bb = ((const float4*)(E0b + (size_t)r*100))[lane];
                    val.x = bb.x + 0.25f*(a.x+c.x+d4.x+e.x);
                    val.y = bb.y + 0.25f*(a.y+c.y+d4.y+e.y);
                    val.z = bb.z + 0.25f*(a.z+c.z+d4.z+e.z);
                    val.w = bb.w + 0.25f*(a.w+c.w+d4.w+e.w);
                }
                *(float4*)&Xs[rr*104 + 4*lane] = val;
            }
        }
        __syncthreads();

        int c3 = (lane < 4) ? 96 + lane : 96;
        int col[4] = {lane, lane+32, lane+64, c3};
        ull acc[3][4];
        #pragma unroll
        for (int k = 0; k < 3; k++)
            #pragma unroll
            for (int c = 0; c < 4; c++) acc[k][c] = 0ull;
        core100p<3>(Ws, Xs, wy, col, acc);

        #pragma unroll
        for (int k = 0; k < 3; k++){
            int rr = wy*3 + k;
            int r = r0 + rr;
            if (r >= NN) continue;
            Xs[rr*104 + col[0]] = ftanh(unpack_sum(acc[k][0]) + bs[col[0]]);
            Xs[rr*104 + col[1]] = ftanh(unpack_sum(acc[k][1]) + bs[col[1]]);
            Xs[rr*104 + col[2]] = ftanh(unpack_sum(acc[k][2]) + bs[col[2]]);
            if (lane < 4) Xs[rr*104 + col[3]] = ftanh(unpack_sum(acc[k][3]) + bs[col[3]]);
        }
        __syncthreads();

        loadW100(aggLW, Ws, tid);
        if (tid < 100) bs[tid] = aggLb[tid];
        __syncthreads();

        #pragma unroll
        for (int k = 0; k < 3; k++)
            #pragma unroll
            for (int c = 0; c < 4; c++) acc[k][c] = 0ull;
        core100p<3>(Ws, Xs, wy, col, acc);

        #pragma unroll
        for (int k = 0; k < 3; k++){
            int r = r0 + wy*3 + k;
            if (r >= NN) continue;
            float* yo = AGG + (size_t)r*100;
            yo[col[0]] = ftanh(unpack_sum(acc[k][0]) + bs[col[0]]);
            yo[col[1]] = ftanh(unpack_sum(acc[k][1]) + bs[col[1]]);
            yo[col[2]] = ftanh(unpack_sum(acc[k][2]) + bs[col[2]]);
            if (lane < 4) yo[col[3]] = ftanh(unpack_sum(acc[k][3]) + bs[col[3]]);
        }
    } else {
        // ---- scores + top-10 branch (vectorized) ----
        float* P    = sm;              // [199][102]
        float* qrow = P + 199*102;     // [8][104]
        float* srow = qrow + 8*104;    // [8][200]
        int*   qidx = (int*)(srow + 8*200);  // [200]
        int sid = bid - NBD;
        int b  = sid & 31;
        int ty = sid >> 5;
        if (tid < TT) qidx[tid] = question[b*TT + tid];
        __syncthreads();
        int tmax = min(TM - 1, ty*8 + 7);
        int rmax = tmax;
        for (int i = tid; i < rmax*50; i += 256) {
            int s = i / 50, d2 = i - s*50;
            float2 v = ((const float2*)(emb_q + (size_t)qidx[s]*DD))[d2];
            *(float2*)&P[s*102 + 2*d2] = v;
        }
        __syncthreads();
        int t = ty*8 + wy;
        if (t >= TM) return;
        int qv = qidx[t + 1];
        for (int d = lane; d < 50; d += 32)
            *(float2*)&qrow[wy*104 + 2*d] = ((const float2*)(emb_q + (size_t)qv*DD))[d];
        __syncwarp();
        const ull* qrU = (const ull*)qrow + wy*52;
        for (int s = lane; s < t; s += 32) {
            const ull* prU = (const ull*)P + s*51;
            ull acc2 = 0ull;
            #pragma unroll 5
            for (int dw = 0; dw < 50; dw++) fma2(acc2, qrU[dw], prU[dw]);
            srow[wy*200 + s] = unpack_sum(acc2);
        }
        __syncwarp();
        int n = b*TM + t;
        int cnt = min(t, KK);
        for (int sel = 0; sel < KK; sel++) {
            if (sel < cnt) {
                float bv = -3.4e38f; unsigned bi = 0xffffffffu;
                for (int s = lane; s < t; s += 32) {
                    float v = srow[wy*200 + s];
                    if (v > bv) { bv = v; bi = (unsigned)s; }
                }
                #pragma unroll
                for (int off = 16; off; off >>= 1) {
                    float    ov = __shfl_down_sync(0xffffffffu, bv, off);
                    unsigned oi = __shfl_down_sync(0xffffffffu, bi, off);
                    if (ov > bv || (ov == bv && oi < bi)) { bv = ov; bi = oi; }
                }
                bi = __shfl_sync(0xffffffffu, bi, 0);
                if (lane == 0) { topk[n*KK + sel] = (int)bi; srow[wy*200 + bi] = -3.4e38f; }
                __syncwarp();
            } else if (lane == 0) {
                topk[n*KK + sel] = -1;
            }
        }
    }
}

// ---------------- LSTM gates, column-parallel grid 597 blocks ----------------

__global__ __launch_bounds__(256) void gates_k(
    const int* __restrict__ question, const int* __restrict__ response,
    const int* __restrict__ maskp, const float* __restrict__ emb_q,
    const float* __restrict__ emb_r, const float* __restrict__ AGG,
    const float* __restrict__ Wih, const float* __restrict__ lb,
    float* __restrict__ G){
    extern __shared__ float sm[];
    float* Ws = sm;             // 100 x 202
    float* Xs = sm + 20200;     // 32 x 204
    float* bs = Xs + 32*204;    // 100
    int tid = threadIdx.x, wy = tid >> 5, lane = tid & 31;
    int bid = blockIdx.x;
    int gy = bid / 199;
    int bx = bid - gy*199;
    int ob = (gy == 0) ? 0 : (gy + 1)*100;   // 0, 200, 300
    const float* W = Wih + (size_t)ob*200;

    for (int j = tid; j < 5000; j += 256){
        float4 v = ((const float4*)W)[j];
        int b4 = 4*j; int o = b4/200; int d = b4 - o*200;
        float2* ws = (float2*)&Ws[o*202 + d];
        ws[0] = make_float2(v.x, v.y);
        ws[1] = make_float2(v.z, v.w);
    }
    if (tid < 100) bs[tid] = lb[ob + tid];

    int r0 = bx * 32;
    for (int rr = wy; rr < 32; rr += 8){
        if (lane < 25){
            int r = r0 + rr;
            int b = r / TM, t = r - b*TM;
            int q   = question[b*TT + t];
            int m   = maskp[b*TT + t];
            int rsp = response[b*TT + t];
            const float4* s1 = (const float4*)((m == 1) ? (AGG + (size_t)r*100)
                                                        : (emb_q + (size_t)q*100));
            const float4* s2 = (const float4*)(emb_r + (size_t)rsp*100);
            *(float4*)&Xs[rr*204 + 4*lane]       = s1[lane];
            *(float4*)&Xs[rr*204 + 100 + 4*lane] = s2[lane];
        }
    }
    __syncthreads();

    int c3 = (lane < 4) ? 96 + lane : 96;
    int col[4] = {lane, lane+32, lane+64, c3};
    ull acc[4][4];
    #pragma unroll
    for (int k = 0; k < 4; k++)
        #pragma unroll
        for (int c = 0; c < 4; c++) acc[k][c] = 0ull;

    {
        const ull* WsU = (const ull*)Ws;
        const ull* XsU = (const ull*)Xs;
        const int xbase = wy*4*102;
        ull w[4], x[4], nw[4], nx[4];
        #pragma unroll
        for (int c = 0; c < 4; c++) w[c] = WsU[col[c]*101];
        #pragma unroll
        for (int k = 0; k < 4; k++) x[k] = XsU[xbase + k*102];
        #pragma unroll 1
        for (int dw = 0; dw < 100; dw++){
            int dn = dw + 1;
            #pragma unroll
            for (int c = 0; c < 4; c++) nw[c] = WsU[col[c]*101 + dn];
            #pragma unroll
            for (int k = 0; k < 4; k++) nx[k] = XsU[xbase + k*102 + dn];
            #pragma unroll
            for (int k = 0; k < 4; k++)
                #pragma unroll
                for (int c = 0; c < 4; c++)
                    fma2(acc[k][c], x[k], w[c]);
            #pragma unroll
            for (int c = 0; c < 4; c++) w[c] = nw[c];
            #pragma unroll
            for (int k = 0; k < 4; k++) x[k] = nx[k];
        }
    }

    #pragma unroll
    for (int k = 0; k < 4; k++){
        int r = r0 + wy*4 + k;
        if (r >= NN) continue;
        float* go = G + (size_t)r*400 + ob;
        go[col[0]] = unpack_sum(acc[k][0]) + bs[col[0]];
        go[col[1]] = unpack_sum(acc[k][1]) + bs[col[1]];
        go[col[2]] = unpack_sum(acc[k][2]) + bs[col[2]];
        if (lane < 4) go[col[3]] = unpack_sum(acc[k][3]) + bs[col[3]];
    }
}

// ---------------- LSTM pointwise + output tail (fused) ----------------
__global__ void lstm_pw_k(const float* __restrict__ G, float* __restrict__ L,
                          float* __restrict__ out) {
    int i = blockIdx.x*blockDim.x + threadIdx.x;
    if (i < BB) out[i*TT] = 0.5f;
    if (i >= NN*DD) return;
    int n = i/DD, d = i - n*DD;
    const float* g = G + (size_t)n*400;
    float gi = g[d], gg = g[200+d], go = g[300+d];
    float val = fsig(go) * ftanh(fsig(gi) * ftanh(gg));
    L[i] = val;
    int b = n / TM, t = n - b*TM;
    if (t == TM-1) out[BB*TT + b*DD + d] = val;
}

// ---------------- fused KT affine + attention + output: 4 n's (44 hist rows) / block ----------------

__global__ __launch_bounds__(256) void ktfinal_k(
    const int* __restrict__ question, const int* __restrict__ skidx,
    const int* __restrict__ skmask, const float* __restrict__ emb_q,
    const float* __restrict__ emb_s, const float* __restrict__ L,
    const int* __restrict__ topk, const float* __restrict__ Wq,
    const float* __restrict__ bq, const float* __restrict__ w_att,
    float* __restrict__ out){
    extern __shared__ float sm[];
    float* Ws  = sm;               // 10200
    float* Xs  = sm + 10200;       // 48*104
    float* bs  = Xs + 48*104;      // 100
    float* w2s = bs + 100;         // 100
    float* qsm = w2s + 100;        // 4*104
    float* ktm = qsm + 4*104;      // 48
    float* gvm = ktm + 48;         // 48
    int tid = threadIdx.x, wy = tid >> 5, lane = tid & 31;
    int n0 = blockIdx.x * 4;

    loadW100(Wq, Ws, tid);
    if (tid < 100) { bs[tid] = bq[tid]; w2s[tid] = w_att[100 + tid]; }

    for (int rr = wy; rr < 48; rr += 8){
        if (lane < 25){
            float4 val = make_float4(0.f,0.f,0.f,0.f);
            if (rr < 44){
                int n = n0 + rr/11, s = rr - (rr/11)*11;
                int b = n / TM, t = n - b*TM;
                int cnt = min(t, KK);
                const float* src = nullptr;
                if (s == 0) src = L + (size_t)n*100;
                else if (s-1 < cnt){
                    int idx = topk[n*KK + s - 1];
                    if (idx > 0) src = L + ((size_t)b*TM + idx)*100;
                }
                if (src) val = ((const float4*)src)[lane];
            }
            *(float4*)&Xs[rr*104 + 4*lane] = val;
        }
    }
    if (wy < 4){
        int n = n0 + wy;
        int b = n / TM, t = n - b*TM;
        int qv = question[b*TT + t + 1];
        if (lane < 25){
            float4 v = ((const float4*)(emb_q + (size_t)qv*100))[lane];
            #pragma unroll
            for (int i = 0; i < 4; i++){
                if (skmask[qv*4 + i] != 0){
                    float4 e = ((const float4*)(emb_s + (size_t)skidx[qv*4 + i]*100))[lane];
                    v.x += e.x; v.y += e.y; v.z += e.z; v.w += e.w;
                }
            }
            *(float4*)&qsm[wy*104 + 4*lane] = v;
        }
    }
    __syncthreads();

    int c3 = (lane < 4) ? 96 + lane : 96;
    int col[4] = {lane, lane+32, lane+64, c3};
    ull acc[6][4];
    #pragma unroll
    for (int k = 0; k < 6; k++)
        #pragma unroll
        for (int c = 0; c < 4; c++) acc[k][c] = 0ull;
    core100p<6>(Ws, Xs, wy, col, acc);

    #pragma unroll
    for (int k = 0; k < 6; k++){
        int rr = wy*6 + k;
        if (rr >= 44) continue;
        int nl = rr / 11;
        float o0 = ftanh(unpack_sum(acc[k][0]) + bs[col[0]]);
        float o1 = ftanh(unpack_sum(acc[k][1]) + bs[col[1]]);
        float o2 = ftanh(unpack_sum(acc[k][2]) + bs[col[2]]);
        float o3 = ftanh(unpack_sum(acc[k][3]) + bs[col[3]]);
        float v = o0*w2s[col[0]] + o1*w2s[col[1]] + o2*w2s[col[2]];
        float g = Xs[rr*104+col[0]]*qsm[nl*104+col[0]]
                + Xs[rr*104+col[1]]*qsm[nl*104+col[1]]
                + Xs[rr*104+col[2]]*qsm[nl*104+col[2]];
        if (lane < 4){
            v += o3*w2s[col[3]];
            g += Xs[rr*104+col[3]]*qsm[nl*104+col[3]];
        }
        #pragma unroll
        for (int off = 16; off; off >>= 1){
            v += __shfl_down_sync(0xffffffffu, v, off);
            g += __shfl_down_sync(0xffffffffu, g, off);
        }
        if (lane == 0){ ktm[rr] = v; gvm[rr] = g; }
    }
    __syncthreads();

    if (tid < 4){
        int n = n0 + tid;
        int b = n / TM, t = n - b*TM;
        int cnt = min(t, KK);
        float m = -3.4e38f;
        for (int s = 0; s <= cnt; s++){ float v = ktm[tid*11 + s]; if (v > m) m = v; }
        float Z = 0.f, P = 0.f;
        for (int s = 0; s <= cnt; s++){
            float e = __expf(ktm[tid*11 + s] - m);
            Z += e; P += e*gvm[tid*11 + s];
        }
        out[b*TT + 1 + t] = fsig(__fdividef(P, Z));
    }
}

// ---------------- launch ----------------

extern "C" void kernel_launch(void* const* d_in, const int* in_sizes, int n_in,
                              void* d_out, int out_size) {
    const int*   question = (const int*)d_in[0];
    const int*   response = (const int*)d_in[1];
    const int*   maskp    = (const int*)d_in[2];
    const int*   q_nb     = (const int*)d_in[3];
    const int*   s_nb     = (const int*)d_in[4];
    const int*   skidx    = (const int*)d_in[5];
    const int*   skmask   = (const int*)d_in[6];
    const float* emb_q    = (const float*)d_in[7];
    const float* emb_s    = (const float*)d_in[8];
    const float* emb_r    = (const float*)d_in[9];
    const float* Wih      = (const float*)d_in[10];
    const float* lb       = (const float*)d_in[11];
    const float* aggW     = (const float*)d_in[12];
    const float* aggb     = (const float*)d_in[13];
    const float* aggLW    = (const float*)d_in[14];
    const float* aggLb    = (const float*)d_in[15];
    const float* Wq       = (const float*)d_in[16];
    const float* bq       = (const float*)d_in[17];
    const float* w_att    = (const float*)d_in[20];
    float* out = (float*)d_out;

    float* buf = nullptr; int* topk = nullptr;
    cudaGetSymbolAddress((void**)&buf,  g_buf);
    cudaGetSymbolAddress((void**)&topk, g_topk);

    float* pE2P = buf + OFF_E2P;
    float* pE1T = buf + OFF_E1T;
    float* pE0a = buf + OFF_E0A;
    float* pE1b = buf + OFF_E1B;
    float* pE0b = buf + OFF_E0B;
    float* pAGG = buf + OFF_AGG;
    float* pL   = buf + OFF_L;
    float* pG   = buf + OFF_G;

    const int AFF_SMEM = (10200 + 48*104 + 100)*4;
    const int KTF_SMEM = (10200 + 48*104 + 100 + 100 + 4*104 + 48 + 48)*4;
    const int GAT_SMEM = (20200 + 32*204 + 100)*4;
    const int SCO_SMEM = (199*102 + 8*104 + 8*200 + 200)*4;
    const int D_SMEM   = (10200 + 24*104 + 100)*4;
    const int DS_SMEM  = (SCO_SMEM > D_SMEM) ? SCO_SMEM : D_SMEM;
    cudaFuncSetAttribute(stageB_k,  cudaFuncAttributeMaxDynamicSharedMemorySize, AFF_SMEM);
    cudaFuncSetAttribute(stageC_k,  cudaFuncAttributeMaxDynamicSharedMemorySize, AFF_SMEM);
    cudaFuncSetAttribute(stageDS_k, cudaFuncAttributeMaxDynamicSharedMemorySize, DS_SMEM);
    cudaFuncSetAttribute(gates_k,   cudaFuncAttributeMaxDynamicSharedMemorySize, GAT_SMEM);
    cudaFuncSetAttribute(ktfinal_k, cudaFuncAttributeMaxDynamicSharedMemorySize, KTF_SMEM);

    stageB_k<<<MB0+MB1+NB2, 256, AFF_SMEM>>>(question, q_nb, s_nb, emb_q, emb_s,
                                             aggW, aggb, pE2P, pE1T, pE0a);
    stageC_k<<<MB1+NB2, 256, AFF_SMEM>>>(question, q_nb, pE1T, pE2P, pE0a,
                                         aggW, aggb, pE1b, pE0b);
    stageDS_k<<<NBDS, 256, DS_SMEM>>>(question, q_nb, pE0b, pE1b,
                                      aggW, aggb, aggLW, aggLb, emb_q, pAGG, topk);

    gates_k<<<NGATE, 256, GAT_SMEM>>>(question, response, maskp, emb_q, emb_r,
                                      pAGG, Wih, lb, pG);
    lstm_pw_k<<<(NN*DD + 255)/256, 256>>>(pG, pL, out);

    ktfinal_k<<<NN/4, 256, KTF_SMEM>>>(question, skidx, skmask, emb_q, emb_s,
                                       pL, topk, Wq, bq, w_att, out);
}

// round 16
// speedup vs baseline: 1.2533x; 1.2533x over previous
#include <cuda_runtime.h>
#include <math.h>

#define BB 32
#define TT 200
#define TM 199
#define NN (BB*TM)        // 6368
#define DD 100
#define KK 10
#define NE2 4800
#define NE1 1200

#define MB0 100           // NE2/48
#define MB1 25            // NE1/48
#define NB2 133           // ceil(NN/48)
#define NBD 266           // ceil(NN/24)
#define NGATE 597
#define NSCOR 800

typedef unsigned long long ull;

// ---------------- scratch ----------------
__device__ float g_buf[5820800];
__device__ int   g_topk[NN*KK];

static constexpr size_t OFF_E2P = 0;          // NE2*100
static constexpr size_t OFF_E1T = 480000;     // NE1*100
static constexpr size_t OFF_E0A = 600000;     // NN*100
static constexpr size_t OFF_E1B = 1236800;    // NE1*100
static constexpr size_t OFF_E0B = 1356800;    // NN*100
static constexpr size_t OFF_AGG = 1993600;    // NN*100
static constexpr size_t OFF_L   = 2630400;    // NN*100
static constexpr size_t OFF_G   = 3267200;    // NN*400
static constexpr size_t OFF_KTL = 5814400;    // NN

// ---------------- helpers ----------------
__device__ __forceinline__ void fma2(ull& a, ull x, ull w){
    asm("fma.rn.f32x2 %0, %1, %2, %0;" : "+l"(a) : "l"(x), "l"(w));
}
__device__ __forceinline__ float unpack_sum(ull a){
    float lo = __int_as_float((int)(unsigned int)a);
    float hi = __int_as_float((int)(unsigned int)(a >> 32));
    return lo + hi;
}
__device__ __forceinline__ float ftanh(float x){
    float e = __expf(2.f*x);
    return 1.f - __fdividef(2.f, e + 1.f);
}
__device__ __forceinline__ float fsig(float x){
    return __fdividef(1.f, 1.f + __expf(-x));
}

// load 100x100 W into smem pitch 102 (51 ull words; conflict-free LDS.64)
__device__ __forceinline__ void loadW100(const float* __restrict__ W, float* Ws, int tid){
    for (int j = tid; j < 2500; j += 256){
        float4 v = ((const float4*)W)[j];
        int b4 = 4*j; int o = b4/100; int d = b4 - o*100;
        float2* ws = (float2*)&Ws[o*102 + d];
        ws[0] = make_float2(v.x, v.y);
        ws[1] = make_float2(v.z, v.w);
    }
}

// Software-pipelined KR-rows-per-thread 100-d FFMA core.
template<int KR>
__device__ __forceinline__ void core100p(const float* Ws, const float* Xs, int wy,
                                         const int* col, ull (*acc)[4]){
    const ull* WsU = (const ull*)Ws;
    const ull* XsU = (const ull*)Xs;
    const int xbase = wy*KR*52;
    ull w[4], x[KR], nw[4], nx[KR];
    #pragma unroll
    for (int c = 0; c < 4; c++) w[c] = WsU[col[c]*51];
    #pragma unroll
    for (int k = 0; k < KR; k++) x[k] = XsU[xbase + k*52];
    #pragma unroll 1
    for (int dw = 0; dw < 50; dw++){
        int dn = dw + 1;
        #pragma unroll
        for (int c = 0; c < 4; c++) nw[c] = WsU[col[c]*51 + dn];
        #pragma unroll
        for (int k = 0; k < KR; k++) nx[k] = XsU[xbase + k*52 + dn];
        #pragma unroll
        for (int k = 0; k < KR; k++)
            #pragma unroll
            for (int c = 0; c < 4; c++)
                fma2(acc[k][c], x[k], w[c]);
        #pragma unroll
        for (int c = 0; c < 4; c++) w[c] = nw[c];
        #pragma unroll
        for (int k = 0; k < KR; k++) x[k] = nx[k];
    }
}

// ---------------- stage B: deduped gather + affine ----------------

__global__ __launch_bounds__(256) void stageB_k(
    const int* __restrict__ question, const int* __restrict__ q_nb,
    const int* __restrict__ s_nb, const float* __restrict__ emb_q,
    const float* __restrict__ emb_s, const float* __restrict__ aggW,
    const float* __restrict__ aggb, float* __restrict__ E2P,
    float* __restrict__ E1T, float* __restrict__ E0){
    extern __shared__ float sm[];
    float* Ws = sm;            // 10200
    float* Xs = sm + 10200;    // 48*104
    float* bs = Xs + 48*104;   // 100
    int tid = threadIdx.x, wy = tid >> 5, lane = tid & 31;
    int bid = blockIdx.x;

    int seg, r0, R; const float* W; const float* bias; float* Y;
    if (bid < MB0)            { seg=0; r0=bid*48;           R=NE2; W=aggW+20000; bias=aggb+200; Y=E2P; }
    else if (bid < MB0+MB1)   { seg=1; r0=(bid-MB0)*48;     R=NE1; W=aggW+10000; bias=aggb+100; Y=E1T; }
    else                      { seg=2; r0=(bid-MB0-MB1)*48; R=NN;  W=aggW;       bias=aggb;     Y=E0; }

    loadW100(W, Ws, tid);
    if (tid < 100) bs[tid] = bias[tid];

    for (int rr = wy; rr < 48; rr += 8){
        if (lane < 25){
            int r = r0 + rr;
            float4 val = make_float4(0.f,0.f,0.f,0.f);
            if (r < R){
                const float* basep; const int* nb; const float* tbl;
                if (seg == 0){
                    int q2 = s_nb[r];
                    basep = emb_q + (size_t)q2*DD; nb = q_nb + q2*4; tbl = emb_s;
                } else if (seg == 1){
                    basep = emb_s + (size_t)r*DD; nb = s_nb + r*4; tbl = emb_q;
                } else {
                    int b = r / TM, t = r - b*TM;
                    int q = question[b*TT + t];
                    basep = emb_q + (size_t)q*DD; nb = q_nb + q*4; tbl = emb_s;
                }
                int i0 = nb[0], i1 = nb[1], i2 = nb[2], i3 = nb[3];
                float4 bb = ((const float4*)basep)[lane];
                float4 a = ((const float4*)(tbl + (size_t)i0*DD))[lane];
                float4 c = ((const float4*)(tbl + (size_t)i1*DD))[lane];
                float4 d = ((const float4*)(tbl + (size_t)i2*DD))[lane];
                float4 e = ((const float4*)(tbl + (size_t)i3*DD))[lane];
                val.x = bb.x + 0.25f*(a.x+c.x+d.x+e.x);
                val.y = bb.y + 0.25f*(a.y+c.y+d.y+e.y);
                val.z = bb.z + 0.25f*(a.z+c.z+d.z+e.z);
                val.w = bb.w + 0.25f*(a.w+c.w+d.w+e.w);
            }
            *(float4*)&Xs[rr*104 + 4*lane] = val;
        }
    }
    __syncthreads();

    int c3 = (lane < 4) ? 96 + lane : 96;
    int col[4] = {lane, lane+32, lane+64, c3};
    ull acc[6][4];
    #pragma unroll
    for (int k = 0; k < 6; k++)
        #pragma unroll
        for (int c = 0; c < 4; c++) acc[k][c] = 0ull;
    core100p<6>(Ws, Xs, wy, col, acc);

    #pragma unroll
    for (int k = 0; k < 6; k++){
        int r = r0 + wy*6 + k;
        if (r >= R) continue;
        float* yo = Y + (size_t)r*100;
        yo[col[0]] = ftanh(unpack_sum(acc[k][0]) + bs[col[0]]);
        yo[col[1]] = ftanh(unpack_sum(acc[k][1]) + bs[col[1]]);
        yo[col[2]] = ftanh(unpack_sum(acc[k][2]) + bs[col[2]]);
        if (lane < 4) yo[col[3]] = ftanh(unpack_sum(acc[k][3]) + bs[col[3]]);
    }
}

// ---------------- stage C ----------------

__global__ __launch_bounds__(256) void stageC_k(
    const int* __restrict__ question, const int* __restrict__ q_nb,
    const float* __restrict__ E1T, const float* __restrict__ E2P,
    const float* __restrict__ E0a,
    const float* __restrict__ aggW, const float* __restrict__ aggb,
    float* __restrict__ E1bT, float* __restrict__ E0b){
    extern __shared__ float sm[];
    float* Ws = sm;
    float* Xs = sm + 10200;
    float* bs = Xs + 48*104;
    int tid = threadIdx.x, wy = tid >> 5, lane = tid & 31;
    int bid = blockIdx.x;

    int seg, r0, R; const float* W; const float* bias; float* Y;
    if (bid < MB1){ seg=1; r0=bid*48;        R=NE1; W=aggW+10000; bias=aggb+100; Y=E1bT; }
    else          { seg=2; r0=(bid-MB1)*48;  R=NN;  W=aggW;       bias=aggb;     Y=E0b; }

    loadW100(W, Ws, tid);
    if (tid < 100) bs[tid] = bias[tid];

    for (int rr = wy; rr < 48; rr += 8){
        if (lane < 25){
            int r = r0 + rr;
            float4 val = make_float4(0.f,0.f,0.f,0.f);
            if (r < R){
                float4 a, c, d4, e, bb;
                if (seg == 1){
                    const float4* kp = (const float4*)(E2P + (size_t)r*400);
                    a = kp[lane]; c = kp[25+lane]; d4 = kp[50+lane]; e = kp[75+lane];
                    bb = ((const float4*)(E1T + (size_t)r*100))[lane];
                } else {
                    int b = r / TM, t = r - b*TM;
                    int q = question[b*TT + t];
                    const int* nb = q_nb + q*4;
                    a  = ((const float4*)(E1T + (size_t)nb[0]*100))[lane];
                    c  = ((const float4*)(E1T + (size_t)nb[1]*100))[lane];
                    d4 = ((const float4*)(E1T + (size_t)nb[2]*100))[lane];
                    e  = ((const float4*)(E1T + (size_t)nb[3]*100))[lane];
                    bb = ((const float4*)(E0a + (size_t)r*100))[lane];
                }
                val.x = bb.x + 0.25f*(a.x+c.x+d4.x+e.x);
                val.y = bb.y + 0.25f*(a.y+c.y+d4.y+e.y);
                val.z = bb.z + 0.25f*(a.z+c.z+d4.z+e.z);
                val.w = bb.w + 0.25f*(a.w+c.w+d4.w+e.w);
            }
            *(float4*)&Xs[rr*104 + 4*lane] = val;
        }
    }
    __syncthreads();

    int c3 = (lane < 4) ? 96 + lane : 96;
    int col[4] = {lane, lane+32, lane+64, c3};
    ull acc[6][4];
    #pragma unroll
    for (int k = 0; k < 6; k++)
        #pragma unroll
        for (int c = 0; c < 4; c++) acc[k][c] = 0ull;
    core100p<6>(Ws, Xs, wy, col, acc);

    #pragma unroll
    for (int k = 0; k < 6; k++){
        int r = r0 + wy*6 + k;
        if (r >= R) continue;
        float* yo = Y + (size_t)r*100;
        yo[col[0]] = ftanh(unpack_sum(acc[k][0]) + bs[col[0]]);
        yo[col[1]] = ftanh(unpack_sum(acc[k][1]) + bs[col[1]]);
        yo[col[2]] = ftanh(unpack_sum(acc[k][2]) + bs[col[2]]);
        if (lane < 4) yo[col[3]] = ftanh(unpack_sum(acc[k][3]) + bs[col[3]]);
    }
}

// ---------------- stage D: chained double affine, 24-row tiles ----------------

__global__ __launch_bounds__(256) void stageD_k(
    const int* __restrict__ question, const int* __restrict__ q_nb,
    const float* __restrict__ E0b, const float* __restrict__ E1bT,
    const float* __restrict__ aggW, const float* __restrict__ aggb,
    const float* __restrict__ aggLW, const float* __restrict__ aggLb,
    float* __restrict__ AGG){
    extern __shared__ float sm[];
    float* Ws = sm;            // 10200
    float* Xs = sm + 10200;    // 24*104
    float* bs = Xs + 24*104;   // 100
    int tid = threadIdx.x, wy = tid >> 5, lane = tid & 31;
    int r0 = blockIdx.x * 24;

    loadW100(aggW, Ws, tid);
    if (tid < 100) bs[tid] = aggb[tid];

    for (int rr = wy; rr < 24; rr += 8){
        if (lane < 25){
            int r = r0 + rr;
            float4 val = make_float4(0.f,0.f,0.f,0.f);
            if (r < NN){
                int b = r / TM, t = r - b*TM;
                int q = question[b*TT + t];
                const int* nb = q_nb + q*4;
                float4 a  = ((const float4*)(E1bT + (size_t)nb[0]*100))[lane];
                float4 c  = ((const float4*)(E1bT + (size_t)nb[1]*100))[lane];
                float4 d4 = ((const float4*)(E1bT + (size_t)nb[2]*100))[lane];
                float4 e  = ((const float4*)(E1bT + (size_t)nb[3]*100))[lane];
                float4 bb = ((const float4*)(E0b + (size_t)r*100))[lane];
                val.x = bb.x + 0.25f*(a.x+c.x+d4.x+e.x);
                val.y = bb.y + 0.25f*(a.y+c.y+d4.y+e.y);
                val.z = bb.z + 0.25f*(a.z+c.z+d4.z+e.z);
                val.w = bb.w + 0.25f*(a.w+c.w+d4.w+e.w);
            }
            *(float4*)&Xs[rr*104 + 4*lane] = val;
        }
    }
    __syncthreads();

    int c3 = (lane < 4) ? 96 + lane : 96;
    int col[4] = {lane, lane+32, lane+64, c3};
    ull acc[3][4];
    #pragma unroll
    for (int k = 0; k < 3; k++)
        #pragma unroll
        for (int c = 0; c < 4; c++) acc[k][c] = 0ull;
    core100p<3>(Ws, Xs, wy, col, acc);

    #pragma unroll
    for (int k = 0; k < 3; k++){
        int rr = wy*3 + k;
        int r = r0 + rr;
        if (r >= NN) continue;
        Xs[rr*104 + col[0]] = ftanh(unpack_sum(acc[k][0]) + bs[col[0]]);
        Xs[rr*104 + col[1]] = ftanh(unpack_sum(acc[k][1]) + bs[col[1]]);
        Xs[rr*104 + col[2]] = ftanh(unpack_sum(acc[k][2]) + bs[col[2]]);
        if (lane < 4) Xs[rr*104 + col[3]] = ftanh(unpack_sum(acc[k][3]) + bs[col[3]]);
    }
    __syncthreads();

    loadW100(aggLW, Ws, tid);
    if (tid < 100) bs[tid] = aggLb[tid];
    __syncthreads();

    #pragma unroll
    for (int k = 0; k < 3; k++)
        #pragma unroll
        for (int c = 0; c < 4; c++) acc[k][c] = 0ull;
    core100p<3>(Ws, Xs, wy, col, acc);

    #pragma unroll
    for (int k = 0; k < 3; k++){
        int r = r0 + wy*3 + k;
        if (r >= NN) continue;
        float* yo = AGG + (size_t)r*100;
        yo[col[0]] = ftanh(unpack_sum(acc[k][0]) + bs[col[0]]);
        yo[col[1]] = ftanh(unpack_sum(acc[k][1]) + bs[col[1]]);
        yo[col[2]] = ftanh(unpack_sum(acc[k][2]) + bs[col[2]]);
        if (lane < 4) yo[col[3]] = ftanh(unpack_sum(acc[k][3]) + bs[col[3]]);
    }
}

// ---------------- FUSED: LSTM gates (blocks 0..596) + scores/top-10 (blocks 597..1396) ----------------

__global__ __launch_bounds__(256) void gatesScores_k(
    const int* __restrict__ question, const int* __restrict__ response,
    const int* __restrict__ maskp, const float* __restrict__ emb_q,
    const float* __restrict__ emb_r, const float* __restrict__ AGG,
    const float* __restrict__ Wih, const float* __restrict__ lb,
    float* __restrict__ G, int* __restrict__ topk){
    extern __shared__ float sm[];
    int tid = threadIdx.x, wy = tid >> 5, lane = tid & 31;
    int bid = blockIdx.x;

    if (bid < NGATE){
        float* Ws = sm;             // 100 x 202
        float* Xs = sm + 20200;     // 32 x 204
        float* bs = Xs + 32*204;    // 100
        int gy = bid / 199;
        int bx = bid - gy*199;
        int ob = (gy == 0) ? 0 : (gy + 1)*100;   // 0, 200, 300
        const float* W = Wih + (size_t)ob*200;

        for (int j = tid; j < 5000; j += 256){
            float4 v = ((const float4*)W)[j];
            int b4 = 4*j; int o = b4/200; int d = b4 - o*200;
            float2* ws = (float2*)&Ws[o*202 + d];
            ws[0] = make_float2(v.x, v.y);
            ws[1] = make_float2(v.z, v.w);
        }
        if (tid < 100) bs[tid] = lb[ob + tid];

        int r0 = bx * 32;
        for (int rr = wy; rr < 32; rr += 8){
            if (lane < 25){
                int r = r0 + rr;
                int b = r / TM, t = r - b*TM;
                int q   = question[b*TT + t];
                int m   = maskp[b*TT + t];
                int rsp = response[b*TT + t];
                const float4* s1 = (const float4*)((m == 1) ? (AGG + (size_t)r*100)
                                                            : (emb_q + (size_t)q*100));
                const float4* s2 = (const float4*)(emb_r + (size_t)rsp*100);
                *(float4*)&Xs[rr*204 + 4*lane]       = s1[lane];
                *(float4*)&Xs[rr*204 + 100 + 4*lane] = s2[lane];
            }
        }
        __syncthreads();

        int c3 = (lane < 4) ? 96 + lane : 96;
        int col[4] = {lane, lane+32, lane+64, c3};
        ull acc[4][4];
        #pragma unroll
        for (int k = 0; k < 4; k++)
            #pragma unroll
            for (int c = 0; c < 4; c++) acc[k][c] = 0ull;

        {
            const ull* WsU = (const ull*)Ws;
            const ull* XsU = (const ull*)Xs;
            const int xbase = wy*4*102;
            ull w[4], x[4], nw[4], nx[4];
            #pragma unroll
            for (int c = 0; c < 4; c++) w[c] = WsU[col[c]*101];
            #pragma unroll
            for (int k = 0; k < 4; k++) x[k] = XsU[xbase + k*102];
            #pragma unroll 1
            for (int dw = 0; dw < 100; dw++){
                int dn = dw + 1;
                #pragma unroll
                for (int c = 0; c < 4; c++) nw[c] = WsU[col[c]*101 + dn];
                #pragma unroll
                for (int k = 0; k < 4; k++) nx[k] = XsU[xbase + k*102 + dn];
                #pragma unroll
                for (int k = 0; k < 4; k++)
                    #pragma unroll
                    for (int c = 0; c < 4; c++)
                        fma2(acc[k][c], x[k], w[c]);
                #pragma unroll
                for (int c = 0; c < 4; c++) w[c] = nw[c];
                #pragma unroll
                for (int k = 0; k < 4; k++) x[k] = nx[k];
            }
        }

        #pragma unroll
        for (int k = 0; k < 4; k++){
            int r = r0 + wy*4 + k;
            if (r >= NN) continue;
            float* go = G + (size_t)r*400 + ob;
            go[col[0]] = unpack_sum(acc[k][0]) + bs[col[0]];
            go[col[1]] = unpack_sum(acc[k][1]) + bs[col[1]];
            go[col[2]] = unpack_sum(acc[k][2]) + bs[col[2]];
            if (lane < 4) go[col[3]] = unpack_sum(acc[k][3]) + bs[col[3]];
        }
    } else {
        float* P    = sm;              // [199][102]
        float* qrow = P + 199*102;     // [8][104]
        float* srow = qrow + 8*104;    // [8][200]
        int*   qidx = (int*)(srow + 8*200);  // [200]
        int sid = bid - NGATE;
        int b  = sid & 31;
        int ty = sid >> 5;
        if (tid < TT) qidx[tid] = question[b*TT + tid];
        __syncthreads();
        int tmax = min(TM - 1, ty*8 + 7);
        int rmax = tmax;
        for (int i = tid; i < rmax*50; i += 256) {
            int s = i / 50, d2 = i - s*50;
            float2 v = ((const float2*)(emb_q + (size_t)qidx[s]*DD))[d2];
            *(float2*)&P[s*102 + 2*d2] = v;
        }
        __syncthreads();
        int t = ty*8 + wy;
        if (t >= TM) return;
        int qv = qidx[t + 1];
        for (int d = lane; d < 50; d += 32)
            *(float2*)&qrow[wy*104 + 2*d] = ((const float2*)(emb_q + (size_t)qv*DD))[d];
        __syncwarp();
        const ull* qrU = (const ull*)qrow + wy*52;
        for (int s = lane; s < t; s += 32) {
            const ull* prU = (const ull*)P + s*51;
            ull acc2 = 0ull;
            #pragma unroll 5
            for (int dw = 0; dw < 50; dw++) fma2(acc2, qrU[dw], prU[dw]);
            srow[wy*200 + s] = unpack_sum(acc2);
        }
        __syncwarp();
        int n = b*TM + t;
        int cnt = min(t, KK);
        for (int sel = 0; sel < KK; sel++) {
            if (sel < cnt) {
                float bv = -3.4e38f; unsigned bi = 0xffffffffu;
                for (int s = lane; s < t; s += 32) {
                    float v = srow[wy*200 + s];
                    if (v > bv) { bv = v; bi = (unsigned)s; }
                }
                #pragma unroll
                for (int off = 16; off; off >>= 1) {
                    float    ov = __shfl_down_sync(0xffffffffu, bv, off);
                    unsigned oi = __shfl_down_sync(0xffffffffu, bi, off);
                    if (ov > bv || (ov == bv && oi < bi)) { bv = ov; bi = oi; }
                }
                bi = __shfl_sync(0xffffffffu, bi, 0);
                if (lane == 0) { topk[n*KK + sel] = (int)bi; srow[wy*200 + bi] = -3.4e38f; }
                __syncwarp();
            } else if (lane == 0) {
                topk[n*KK + sel] = -1;
            }
        }
    }
}

// ---------------- LSTM pointwise + output tail (fused) ----------------
__global__ void lstm_pw_k(const float* __restrict__ G, float* __restrict__ L,
                          float* __restrict__ out) {
    int i = blockIdx.x*blockDim.x + threadIdx.x;
    if (i < BB) out[i*TT] = 0.5f;
    if (i >= NN*DD) return;
    int n = i/DD, d = i - n*DD;
    const float* g = G + (size_t)n*400;
    float gi = g[d], gg = g[200+d], go = g[300+d];
    float val = fsig(go) * ftanh(fsig(gi) * ftanh(gg));
    L[i] = val;
    int b = n / TM, t = n - b*TM;
    if (t == TM-1) out[BB*TT + b*DD + d] = val;
}

// ---------------- ktL: deduped attention-key scalar per L row ----------------
// ktL[r] = dot(tanh(L[r] @ Wq^T + bq), w_att[100:])  — 133 blocks of 48 rows.

__global__ __launch_bounds__(256) void ktL_k(
    const float* __restrict__ L, const float* __restrict__ Wq,
    const float* __restrict__ bq, const float* __restrict__ w_att,
    float* __restrict__ ktL){
    extern __shared__ float sm[];
    float* Ws  = sm;               // 10200
    float* Xs  = sm + 10200;       // 48*104
    float* bs  = Xs + 48*104;      // 100
    float* w2s = bs + 100;         // 100
    int tid = threadIdx.x, wy = tid >> 5, lane = tid & 31;
    int r0 = blockIdx.x * 48;

    loadW100(Wq, Ws, tid);
    if (tid < 100) { bs[tid] = bq[tid]; w2s[tid] = w_att[100 + tid]; }

    for (int rr = wy; rr < 48; rr += 8){
        if (lane < 25){
            int r = r0 + rr;
            float4 val = make_float4(0.f,0.f,0.f,0.f);
            if (r < NN) val = ((const float4*)(L + (size_t)r*100))[lane];
            *(float4*)&Xs[rr*104 + 4*lane] = val;
        }
    }
    __syncthreads();

    int c3 = (lane < 4) ? 96 + lane : 96;
    int col[4] = {lane, lane+32, lane+64, c3};
    ull acc[6][4];
    #pragma unroll
    for (int k = 0; k < 6; k++)
        #pragma unroll
        for (int c = 0; c < 4; c++) acc[k][c] = 0ull;
    core100p<6>(Ws, Xs, wy, col, acc);

    #pragma unroll
    for (int k = 0; k < 6; k++){
        int r = r0 + wy*6 + k;
        float o0 = ftanh(unpack_sum(acc[k][0]) + bs[col[0]]);
        float o1 = ftanh(unpack_sum(acc[k][1]) + bs[col[1]]);
        float o2 = ftanh(unpack_sum(acc[k][2]) + bs[col[2]]);
        float o3 = ftanh(unpack_sum(acc[k][3]) + bs[col[3]]);
        float v = o0*w2s[col[0]] + o1*w2s[col[1]] + o2*w2s[col[2]];
        if (lane < 4) v += o3*w2s[col[3]];
        #pragma unroll
        for (int off = 16; off; off >>= 1)
            v += __shfl_down_sync(0xffffffffu, v, off);
        if (lane == 0 && r < NN) ktL[r] = v;
    }
}

// ---------------- final attention: kt gathered from ktL; gv dots from L ----------------

__global__ void final_k(const int* __restrict__ question, const int* __restrict__ skidx,
                        const int* __restrict__ skmask, const float* __restrict__ emb_q,
                        const float* __restrict__ emb_s, const float* __restrict__ L,
                        const int* __restrict__ topk, const float* __restrict__ ktL,
                        const float* __restrict__ bq, const float* __restrict__ w_att,
                        float* __restrict__ out) {
    int n = blockIdx.x*4 + (threadIdx.x>>5);
    if (n >= NN) return;
    int lane = threadIdx.x & 31;
    int b = n / TM, t = n - b*TM;
    int qv = question[b*TT + t + 1];
    float qs[4];
    #pragma unroll
    for (int k = 0; k < 4; k++) {
        int d = lane + 32*k;
        float v = 0.f;
        if (d < DD) {
            v = emb_q[(size_t)qv*DD + d];
            #pragma unroll
            for (int i = 0; i < 4; i++)
                if (skmask[qv*4 + i] != 0) v += emb_s[(size_t)skidx[qv*4 + i]*DD + d];
        }
        qs[k] = v;
    }
    // kt0 = dot(tanh(bq), w2): identical lane/column order to the GEMM epilogue on a zero row
    float kt0;
    {
        float v = 0.f;
        #pragma unroll
        for (int k = 0; k < 4; k++) {
            int d = lane + 32*k;
            if (d < DD) v += ftanh(bq[d]) * w_att[DD + d];
        }
        #pragma unroll
        for (int off = 16; off; off >>= 1)
            v += __shfl_down_sync(0xffffffffu, v, off);
        kt0 = v;   // valid on lane 0
    }
    int cnt = min(t, KK);
    float kt[11], gv[11];
    #pragma unroll
    for (int s = 0; s < 11; s++) {
        const float* src = nullptr; int mi = -1;
        if (s == 0) { mi = n; src = L + (size_t)n*DD; }
        else if (s-1 < cnt) {
            int idx = topk[n*KK + s - 1];
            if (idx > 0) { mi = b*TM + idx; src = L + (size_t)mi*DD; }
        }
        float g = 0.f;
        if (src) {
            #pragma unroll
            for (int k = 0; k < 4; k++) {
                int d = lane + 32*k;
                if (d < DD) g += qs[k]*src[d];
            }
            #pragma unroll
            for (int off = 16; off; off >>= 1)
                g += __shfl_down_sync(0xffffffffu, g, off);
        }
        gv[s] = g;
        kt[s] = (lane == 0) ? ((mi >= 0) ? ktL[mi] : kt0) : 0.f;
    }
    if (lane == 0) {
        float m = -3.4e38f;
        #pragma unroll
        for (int s = 0; s < 11; s++) if (s <= cnt && kt[s] > m) m = kt[s];
        float Z = 0.f, P = 0.f;
        #pragma unroll
        for (int s = 0; s < 11; s++)
            if (s <= cnt) { float e = __expf(kt[s]-m); Z += e; P += e*gv[s]; }
        out[b*TT + 1 + t] = fsig(__fdividef(P, Z));
    }
}

// ---------------- launch ----------------

extern "C" void kernel_launch(void* const* d_in, const int* in_sizes, int n_in,
                              void* d_out, int out_size) {
    const int*   question = (const int*)d_in[0];
    const int*   response = (const int*)d_in[1];
    const int*   maskp    = (const int*)d_in[2];
    const int*   q_nb     = (const int*)d_in[3];
    const int*   s_nb     = (const int*)d_in[4];
    const int*   skidx    = (const int*)d_in[5];
    const int*   skmask   = (const int*)d_in[6];
    const float* emb_q    = (const float*)d_in[7];
    const float* emb_s    = (const float*)d_in[8];
    const float* emb_r    = (const float*)d_in[9];
    const float* Wih      = (const float*)d_in[10];
    const float* lb       = (const float*)d_in[11];
    const float* aggW     = (const float*)d_in[12];
    const float* aggb     = (const float*)d_in[13];
    const float* aggLW    = (const float*)d_in[14];
    const float* aggLb    = (const float*)d_in[15];
    const float* Wq       = (const float*)d_in[16];
    const float* bq       = (const float*)d_in[17];
    const float* w_att    = (const float*)d_in[20];
    float* out = (float*)d_out;

    float* buf = nullptr; int* topk = nullptr;
    cudaGetSymbolAddress((void**)&buf,  g_buf);
    cudaGetSymbolAddress((void**)&topk, g_topk);

    float* pE2P = buf + OFF_E2P;
    float* pE1T = buf + OFF_E1T;
    float* pE0a = buf + OFF_E0A;
    float* pE1b = buf + OFF_E1B;
    float* pE0b = buf + OFF_E0B;
    float* pAGG = buf + OFF_AGG;
    float* pL   = buf + OFF_L;
    float* pG   = buf + OFF_G;
    float* pKTL = buf + OFF_KTL;

    const int AFF_SMEM = (10200 + 48*104 + 100)*4;
    const int D_SMEM   = (10200 + 24*104 + 100)*4;
    const int KTL_SMEM = (10200 + 48*104 + 100 + 100)*4;
    const int GAT_SMEM = (20200 + 32*204 + 100)*4;
    const int SCO_SMEM = (199*102 + 8*104 + 8*200 + 200)*4;
    const int GSC_SMEM = (GAT_SMEM > SCO_SMEM) ? GAT_SMEM : SCO_SMEM;
    cudaFuncSetAttribute(stageB_k,      cudaFuncAttributeMaxDynamicSharedMemorySize, AFF_SMEM);
    cudaFuncSetAttribute(stageC_k,      cudaFuncAttributeMaxDynamicSharedMemorySize, AFF_SMEM);
    cudaFuncSetAttribute(stageD_k,      cudaFuncAttributeMaxDynamicSharedMemorySize, D_SMEM);
    cudaFuncSetAttribute(gatesScores_k, cudaFuncAttributeMaxDynamicSharedMemorySize, GSC_SMEM);
    cudaFuncSetAttribute(ktL_k,         cudaFuncAttributeMaxDynamicSharedMemorySize, KTL_SMEM);

    stageB_k<<<MB0+MB1+NB2, 256, AFF_SMEM>>>(question, q_nb, s_nb, emb_q, emb_s,
                                             aggW, aggb, pE2P, pE1T, pE0a);
    stageC_k<<<MB1+NB2, 256, AFF_SMEM>>>(question, q_nb, pE1T, pE2P, pE0a,
                                         aggW, aggb, pE1b, pE0b);
    stageD_k<<<NBD, 256, D_SMEM>>>(question, q_nb, pE0b, pE1b,
                                   aggW, aggb, aggLW, aggLb, pAGG);

    gatesScores_k<<<NGATE+NSCOR, 256, GSC_SMEM>>>(question, response, maskp, emb_q, emb_r,
                                                  pAGG, Wih, lb, pG, topk);
    lstm_pw_k<<<(NN*DD + 255)/256, 256>>>(pG, pL, out);

    ktL_k<<<NB2, 256, KTL_SMEM>>>(pL, Wq, bq, w_att, pKTL);
    final_k<<<NN/4, 128>>>(question, skidx, skmask, emb_q, emb_s,
                           pL, topk, pKTL, bq, w_att, out);
}